// round 15
// baseline (speedup 1.0000x reference)
#include <cuda_runtime.h>
#include <cuda_bf16.h>
#include <math.h>
#include <limits.h>

// Problem constants
#define BATCH 4
#define SEQ   4096
#define DIM   1024
#define NH    16
#define DH    64
#define DFF   4096
#define MFEAT 64
#define ROWS  (BATCH*SEQ)          // 16384
#define FROWS (BATCH*SEQ*NH)       // 262144 feature rows
#define DN_C  0.35355339059327373f // 64^{-1/4}
#define RATIO 0.125f               // 1/sqrt(64)
#define EPSK  1e-6f
#define EPSLN 1e-6f

// ---------------- scratch (device globals; no runtime allocation) -----------
__device__ float g_q   [ROWS*DIM];
__device__ float g_k   [ROWS*DIM];
__device__ float g_v   [ROWS*DIM];
__device__ float g_qf  [ROWS*DIM];   // [B,N,H,M] == 16384x1024
__device__ float g_kf  [ROWS*DIM];   // k dash, then kf in place
__device__ float g_diag[FROWS];      // per feature-row diag for k path
__device__ float g_attn[ROWS*DIM];
__device__ float g_ao  [ROWS*DIM];
__device__ float g_out1[ROWS*DIM];
__device__ float g_ffn [ROWS*DIM];
__device__ float g_h   [ROWS*DFF];   // 16384x4096
__device__ float g_kv  [BATCH*NH*MFEAT*DH];
__device__ float g_ksum[BATCH*NH*MFEAT];
__device__ int   g_kmax_enc;

// TF32 rounding (matches XLA/cuBLAS fp32->tf32 operand rounding)
__device__ __forceinline__ float tf32r(float x) {
    float r;
    asm("cvt.rna.tf32.f32 %0, %1;" : "=f"(r) : "f"(x));
    return r;
}

// ordered-int encoding for float atomicMax
__device__ __forceinline__ int enc_f(float f) {
    int i = __float_as_int(f);
    return i >= 0 ? i : (i ^ 0x7fffffff);
}
__device__ __forceinline__ float dec_f(int e) {
    int i = e >= 0 ? e : (e ^ 0x7fffffff);
    return __int_as_float(i);
}

__global__ void init_max_kernel() { g_kmax_enc = INT_MIN; }

// ---------------- SGEMM: C[MxN] = A[MxK] * B[KxN], all row-major ------------
// 128x128 tile, BK=8, 256 threads, 8x8 microtile. TF32-rounded operands,
// fp32 accumulate (emulates XLA tf32 matmul). Dims are multiples of 128.
// EPI: 0 = none, 1 = +bias, 2 = +bias then ELU
template<int EPI>
__global__ void __launch_bounds__(256, 2)
sgemm_kernel(const float* __restrict__ A, const float* __restrict__ B,
             const float* __restrict__ bias, float* __restrict__ C,
             int M, int N, int K) {
    __shared__ float As[8][128];
    __shared__ float Bs[8][128];
    const int tid = threadIdx.x;
    const int bm = blockIdx.y, bn = blockIdx.x;

    const float* Ab = A + (size_t)bm * 128 * K;
    const float* Bb = B + (size_t)bn * 128;

    const int arow = tid >> 1;            // 0..127
    const int acol = (tid & 1) * 4;       // 0 or 4
    const int brow = tid >> 5;            // 0..7
    const int bcol = (tid & 31) * 4;      // 0..124
    const int trow = (tid >> 4) * 8;      // 0..120
    const int tcol = (tid & 15) * 8;      // 0..120

    float acc[8][8];
    #pragma unroll
    for (int i = 0; i < 8; i++)
        #pragma unroll
        for (int j = 0; j < 8; j++) acc[i][j] = 0.f;

    for (int k0 = 0; k0 < K; k0 += 8) {
        float4 a4 = *(const float4*)(Ab + (size_t)arow * K + k0 + acol);
        As[acol + 0][arow] = tf32r(a4.x);
        As[acol + 1][arow] = tf32r(a4.y);
        As[acol + 2][arow] = tf32r(a4.z);
        As[acol + 3][arow] = tf32r(a4.w);
        float4 b4 = *(const float4*)(Bb + (size_t)(k0 + brow) * N + bcol);
        b4.x = tf32r(b4.x); b4.y = tf32r(b4.y);
        b4.z = tf32r(b4.z); b4.w = tf32r(b4.w);
        *(float4*)&Bs[brow][bcol] = b4;
        __syncthreads();
        #pragma unroll
        for (int k = 0; k < 8; k++) {
            float ar[8], br[8];
            *(float4*)&ar[0] = *(const float4*)&As[k][trow];
            *(float4*)&ar[4] = *(const float4*)&As[k][trow + 4];
            *(float4*)&br[0] = *(const float4*)&Bs[k][tcol];
            *(float4*)&br[4] = *(const float4*)&Bs[k][tcol + 4];
            #pragma unroll
            for (int i = 0; i < 8; i++)
                #pragma unroll
                for (int j = 0; j < 8; j++)
                    acc[i][j] = fmaf(ar[i], br[j], acc[i][j]);
        }
        __syncthreads();
    }

    #pragma unroll
    for (int i = 0; i < 8; i++) {
        float* Crow = C + (size_t)(bm * 128 + trow + i) * N + bn * 128 + tcol;
        #pragma unroll
        for (int j = 0; j < 8; j++) {
            float v = acc[i][j];
            if (EPI >= 1) v += bias[bn * 128 + tcol + j];
            if (EPI == 2) v = v > 0.f ? v : expm1f(v);
            Crow[j] = v;
        }
    }
}

// ---------------- k-feature pre-pass: dash + diag + global max(dash) --------
// blockDim (64,4): 4 feature-rows per block.
// dash = dot(round(k*dn), round(proj))   (tf32 operands like reference matmul)
// diag = sum(k^2) * dn^2 / 2             (plain fp32 reduction)
// global max is over DASH (NOT dash - diag), matching reference.
__global__ void feat_dash_k_kernel(const float* __restrict__ k,
                                   const float* __restrict__ proj,
                                   float* __restrict__ kdash,
                                   float* __restrict__ diagbuf) {
    __shared__ float pr[64][65];
    __shared__ float row[4][64];
    __shared__ float red[256];
    const int tx = threadIdx.x, ty = threadIdx.y;
    const int tid = ty * 64 + tx;
    for (int i = tid; i < 64 * 64; i += 256) pr[i >> 6][i & 63] = tf32r(proj[i]);
    const size_t r0 = (size_t)blockIdx.x * 4;
    row[ty][tx] = k[r0 * 64 + ty * 64 + tx];
    __syncthreads();
    float dot = 0.f, ss = 0.f;
    #pragma unroll
    for (int j = 0; j < 64; j++) {
        float v = row[ty][j];
        dot = fmaf(tf32r(v * DN_C), pr[tx][j], dot);
        ss  = fmaf(v, v, ss);
    }
    kdash[(r0 + ty) * 64 + tx] = dot;
    if (tx == 0) diagbuf[r0 + ty] = ss * (DN_C * DN_C * 0.5f);
    red[tid] = dot;
    __syncthreads();
    for (int s = 128; s > 0; s >>= 1) {
        if (tid < s) red[tid] = fmaxf(red[tid], red[tid + s]);
        __syncthreads();
    }
    if (tid == 0) atomicMax(&g_kmax_enc, enc_f(red[0]));
}

// kf = ratio * (exp(dash - diag - mx) + eps), in place
__global__ void exp_k_kernel(float* __restrict__ kf, const float* __restrict__ diagbuf) {
    const float mx = dec_f(g_kmax_enc);
    size_t i = (size_t)blockIdx.x * 256 + threadIdx.x;
    float d = diagbuf[i >> 6];
    kf[i] = RATIO * (expf(kf[i] - d - mx) + EPSK);
}

// ---------------- q-feature: dash + per-row max(dash) + exp, one pass -------
__global__ void feat_q_kernel(const float* __restrict__ q,
                              const float* __restrict__ proj,
                              float* __restrict__ qf) {
    __shared__ float pr[64][65];
    __shared__ float row[4][64];
    __shared__ float red[4][64];
    const int tx = threadIdx.x, ty = threadIdx.y;
    const int tid = ty * 64 + tx;
    for (int i = tid; i < 64 * 64; i += 256) pr[i >> 6][i & 63] = tf32r(proj[i]);
    const size_t r0 = (size_t)blockIdx.x * 4;
    row[ty][tx] = q[r0 * 64 + ty * 64 + tx];
    __syncthreads();
    float dot = 0.f, ss = 0.f;
    #pragma unroll
    for (int j = 0; j < 64; j++) {
        float v = row[ty][j];
        dot = fmaf(tf32r(v * DN_C), pr[tx][j], dot);
        ss  = fmaf(v, v, ss);
    }
    float diag = ss * (DN_C * DN_C * 0.5f);
    red[ty][tx] = dot;                       // max over DASH per row
    __syncthreads();
    for (int s = 32; s > 0; s >>= 1) {
        if (tx < s) red[ty][tx] = fmaxf(red[ty][tx], red[ty][tx + s]);
        __syncthreads();
    }
    float mx = red[ty][0];
    qf[(r0 + ty) * 64 + tx] = RATIO * (expf(dot - diag - mx) + EPSK);
}

// ---------------- kv[b,h] = sum_n kf[n,:]^T v[n,:]; ksum[b,h] = sum_n kf ----
// one block per (b,h); 256 threads; 4x4 microtile on 64x64 output.
// kv contraction uses tf32-rounded operands; ksum is a plain fp32 reduction.
__global__ void kv_ksum_kernel(const float* __restrict__ kf,
                               const float* __restrict__ v,
                               float* __restrict__ kv,
                               float* __restrict__ ksum) {
    __shared__ float kfs[16][64];
    __shared__ float vs[16][64];
    const int bh = blockIdx.x;
    const int b = bh >> 4, h = bh & 15;
    const float* kfb = kf + ((size_t)b * SEQ * NH + h) * 64;
    const float* vb  = v  + ((size_t)b * SEQ * NH + h) * 64;
    const int tid = threadIdx.x;
    const int tm = (tid >> 4) * 4, td = (tid & 15) * 4;
    const int ln = tid >> 6, lm = tid & 63;
    float acc[4][4] = {};
    float asum[4] = {};
    for (int n0 = 0; n0 < SEQ; n0 += 16) {
        __syncthreads();
        #pragma unroll
        for (int it = 0; it < 4; it++) {
            int nn = ln + it * 4;
            size_t off = (size_t)(n0 + nn) * (NH * 64) + lm;
            kfs[nn][lm] = kfb[off];
            vs[nn][lm]  = vb[off];
        }
        __syncthreads();
        #pragma unroll
        for (int nn = 0; nn < 16; nn++) {
            float a[4], ar[4], bb[4];
            #pragma unroll
            for (int i = 0; i < 4; i++) { a[i] = kfs[nn][tm + i]; ar[i] = tf32r(a[i]); }
            #pragma unroll
            for (int j = 0; j < 4; j++) bb[j] = tf32r(vs[nn][td + j]);
            #pragma unroll
            for (int i = 0; i < 4; i++) {
                if (td == 0) asum[i] += a[i];
                #pragma unroll
                for (int j = 0; j < 4; j++)
                    acc[i][j] = fmaf(ar[i], bb[j], acc[i][j]);
            }
        }
    }
    float* kvb = kv + (size_t)bh * 64 * 64;
    #pragma unroll
    for (int i = 0; i < 4; i++)
        #pragma unroll
        for (int j = 0; j < 4; j++)
            kvb[(tm + i) * 64 + td + j] = acc[i][j];
    if ((tid & 15) == 0)
        #pragma unroll
        for (int i = 0; i < 4; i++) ksum[bh * 64 + tm + i] = asum[i];
}

// ---------------- attn[b,n,h,d] = (qf . kv[:,d]) / (qf . ksum) --------------
// grid (64, 256): block = (b,h) x 16-row chunk; 256 threads.
// Both dots use tf32-rounded operands (reference: two einsums).
__global__ void attn_kernel(const float* __restrict__ qf,
                            const float* __restrict__ kv,
                            const float* __restrict__ ksum,
                            float* __restrict__ attn) {
    __shared__ float kvs[64][65];
    __shared__ float kss[64];
    __shared__ float qs[16][64];
    const int bh = blockIdx.x;
    const int b = bh >> 4, h = bh & 15;
    const int n0 = blockIdx.y * 16;
    const int tid = threadIdx.x;
    for (int i = tid; i < 64 * 64; i += 256)
        kvs[i >> 6][i & 63] = tf32r(kv[(size_t)bh * 4096 + i]);
    if (tid < 64) kss[tid] = tf32r(ksum[bh * 64 + tid]);
    const float* qfb = qf + ((size_t)b * SEQ * NH + h) * 64;
    const int ln = tid >> 6, lm = tid & 63;
    #pragma unroll
    for (int it = 0; it < 4; it++)
        qs[ln + it * 4][lm] = tf32r(qfb[(size_t)(n0 + ln + it * 4) * (NH * 64) + lm]);
    __syncthreads();
    const int d = tid & 63;
    const int r = tid >> 6;
    float* ab = attn + ((size_t)b * SEQ * NH + h) * 64;
    #pragma unroll
    for (int it = 0; it < 4; it++) {
        int nn = r + it * 4;
        float num = 0.f, den = 0.f;
        #pragma unroll
        for (int m = 0; m < 64; m++) {
            float qv = qs[nn][m];
            num = fmaf(qv, kvs[m][d], num);
            den = fmaf(qv, kss[m], den);
        }
        ab[(size_t)(n0 + nn) * (NH * 64) + d] = num / den;
    }
}

// ---------------- LayerNorm(a + b) * g + beta, row width 1024 ---------------
__global__ void ln_kernel(const float* __restrict__ a, const float* __restrict__ bres,
                          const float* __restrict__ g, const float* __restrict__ beta,
                          float* __restrict__ out) {
    __shared__ float red[2][8];
    const size_t row = blockIdx.x;
    const int tid = threadIdx.x;  // 256
    float4 x = ((const float4*)(a    + row * DIM))[tid];
    float4 y = ((const float4*)(bres + row * DIM))[tid];
    float4 s;
    s.x = x.x + y.x; s.y = x.y + y.y; s.z = x.z + y.z; s.w = x.w + y.w;
    float sum = s.x + s.y + s.z + s.w;
    float ssq = s.x * s.x + s.y * s.y + s.z * s.z + s.w * s.w;
    #pragma unroll
    for (int o = 16; o > 0; o >>= 1) {
        sum += __shfl_xor_sync(~0u, sum, o);
        ssq += __shfl_xor_sync(~0u, ssq, o);
    }
    const int w = tid >> 5, l = tid & 31;
    if (l == 0) { red[0][w] = sum; red[1][w] = ssq; }
    __syncthreads();
    sum = 0.f; ssq = 0.f;
    #pragma unroll
    for (int i = 0; i < 8; i++) { sum += red[0][i]; ssq += red[1][i]; }
    const float mu = sum * (1.f / DIM);
    const float var = ssq * (1.f / DIM) - mu * mu;
    const float rs = rsqrtf(var + EPSLN);
    float4 gg = ((const float4*)g)[tid];
    float4 bb = ((const float4*)beta)[tid];
    float4 o;
    o.x = (s.x - mu) * rs * gg.x + bb.x;
    o.y = (s.y - mu) * rs * gg.y + bb.y;
    o.z = (s.z - mu) * rs * gg.z + bb.z;
    o.w = (s.w - mu) * rs * gg.w + bb.w;
    ((float4*)(out + row * DIM))[tid] = o;
}

// ---------------- launcher ---------------------------------------------------
extern "C" void kernel_launch(void* const* d_in, const int* in_sizes, int n_in,
                              void* d_out, int out_size) {
    const float* x     = (const float*)d_in[0];
    const float* Wq    = (const float*)d_in[1];
    const float* Wk    = (const float*)d_in[2];
    const float* Wv    = (const float*)d_in[3];
    const float* Wo    = (const float*)d_in[4];
    const float* proj  = (const float*)d_in[5];
    const float* W1    = (const float*)d_in[6];
    const float* b1    = (const float*)d_in[7];
    const float* W2    = (const float*)d_in[8];
    const float* b2    = (const float*)d_in[9];
    const float* ln1g  = (const float*)d_in[10];
    const float* ln1b  = (const float*)d_in[11];
    const float* ln2g  = (const float*)d_in[12];
    const float* ln2b  = (const float*)d_in[13];
    float* out = (float*)d_out;

    float *pq, *pk, *pv, *pqf, *pkf, *pdiag, *pattn, *pao, *pout1, *pffn, *ph, *pkv, *pksum;
    cudaGetSymbolAddress((void**)&pq,    g_q);
    cudaGetSymbolAddress((void**)&pk,    g_k);
    cudaGetSymbolAddress((void**)&pv,    g_v);
    cudaGetSymbolAddress((void**)&pqf,   g_qf);
    cudaGetSymbolAddress((void**)&pkf,   g_kf);
    cudaGetSymbolAddress((void**)&pdiag, g_diag);
    cudaGetSymbolAddress((void**)&pattn, g_attn);
    cudaGetSymbolAddress((void**)&pao,   g_ao);
    cudaGetSymbolAddress((void**)&pout1, g_out1);
    cudaGetSymbolAddress((void**)&pffn,  g_ffn);
    cudaGetSymbolAddress((void**)&ph,    g_h);
    cudaGetSymbolAddress((void**)&pkv,   g_kv);
    cudaGetSymbolAddress((void**)&pksum, g_ksum);

    // 1) QKV projections: [16384,1024] x [1024,1024]
    dim3 g_dk(DIM / 128, ROWS / 128);
    sgemm_kernel<0><<<g_dk, 256>>>(x, Wq, nullptr, pq, ROWS, DIM, DIM);
    sgemm_kernel<0><<<g_dk, 256>>>(x, Wk, nullptr, pk, ROWS, DIM, DIM);
    sgemm_kernel<0><<<g_dk, 256>>>(x, Wv, nullptr, pv, ROWS, DIM, DIM);

    // 2) k-feature dash + diag + global max(dash)
    init_max_kernel<<<1, 1>>>();
    feat_dash_k_kernel<<<FROWS / 4, dim3(64, 4)>>>(pk, proj, pkf, pdiag);
    exp_k_kernel<<<(ROWS * DIM) / 256, 256>>>(pkf, pdiag);

    // 3) q-features (row max local)
    feat_q_kernel<<<FROWS / 4, dim3(64, 4)>>>(pq, proj, pqf);

    // 4) kv + ksum
    kv_ksum_kernel<<<BATCH * NH, 256>>>(pkf, pv, pkv, pksum);

    // 5) attention combine -> attn buffer [16384, 1024]
    attn_kernel<<<dim3(BATCH * NH, SEQ / 16), 256>>>(pqf, pkv, pksum, pattn);

    // 6) output projection Wo
    sgemm_kernel<0><<<g_dk, 256>>>(pattn, Wo, nullptr, pao, ROWS, DIM, DIM);

    // 7) LN1(x + attn_out)
    ln_kernel<<<ROWS, 256>>>(x, pao, ln1g, ln1b, pout1);

    // 8) FFN: h = elu(out1 @ W1 + b1)
    dim3 g_f1(DFF / 128, ROWS / 128);
    sgemm_kernel<2><<<g_f1, 256>>>(pout1, W1, b1, ph, ROWS, DFF, DIM);

    // 9) ffn = h @ W2 + b2
    sgemm_kernel<1><<<g_dk, 256>>>(ph, W2, b2, pffn, ROWS, DIM, DFF);

    // 10) LN2(out1 + ffn) -> output
    ln_kernel<<<ROWS, 256>>>(pout1, pffn, ln2g, ln2b, out);

    (void)in_sizes; (void)n_in; (void)out_size;
}

// round 16
// speedup vs baseline: 2.1604x; 2.1604x over previous
#include <cuda_runtime.h>
#include <cuda_bf16.h>
#include <math.h>
#include <limits.h>

// Problem constants
#define BATCH 4
#define SEQ   4096
#define DIM   1024
#define NH    16
#define DH    64
#define DFF   4096
#define MFEAT 64
#define ROWS  (BATCH*SEQ)          // 16384
#define FROWS (BATCH*SEQ*NH)       // 262144 feature rows
#define DN_C  0.35355339059327373f // 64^{-1/4}
#define RATIO 0.125f               // 1/sqrt(64)
#define EPSK  1e-6f
#define EPSLN 1e-6f
#define KVCH  8                    // kv partial chunks

// ---------------- scratch (device globals; no runtime allocation) -----------
__device__ float g_q   [ROWS*DIM];
__device__ float g_k   [ROWS*DIM];
__device__ float g_v   [ROWS*DIM];
__device__ float g_qf  [ROWS*DIM];
__device__ float g_kf  [ROWS*DIM];   // k dash, then kf in place
__device__ float g_diag[FROWS];
__device__ float g_attn[ROWS*DIM];
__device__ float g_ao  [ROWS*DIM];
__device__ float g_out1[ROWS*DIM];
__device__ float g_ffn [ROWS*DIM];
__device__ float g_h   [ROWS*DFF];
__device__ float g_kv  [BATCH*NH*MFEAT*DH];
__device__ float g_ksum[BATCH*NH*MFEAT];
__device__ float g_kvp [KVCH*BATCH*NH*MFEAT*DH];
__device__ float g_ksp [KVCH*BATCH*NH*MFEAT];
__device__ int   g_kmax_enc;

// TF32 rounding (matches XLA/cuBLAS fp32->tf32 operand rounding)
__device__ __forceinline__ float tf32r(float x) {
    float r;
    asm("cvt.rna.tf32.f32 %0, %1;" : "=f"(r) : "f"(x));
    return r;
}

__device__ __forceinline__ int enc_f(float f) {
    int i = __float_as_int(f);
    return i >= 0 ? i : (i ^ 0x7fffffff);
}
__device__ __forceinline__ float dec_f(int e) {
    int i = e >= 0 ? e : (e ^ 0x7fffffff);
    return __int_as_float(i);
}

__global__ void init_max_kernel() { g_kmax_enc = INT_MIN; }

// ---------------- tf32 tensor-core GEMM -------------------------------------
// C[MxN] = A[MxK] * B[KxN], row-major. Operands tf32(rna)-rounded, fp32 accum
// (bit-compatible with XLA tf32 matmul). 128x128 block tile, BK=16,
// 8 warps (2x4), warp tile 64x32 via m16n8k8 fragments. Double-buffered smem.
// EPI: 0 = none, 1 = +bias, 2 = +bias then ELU
__device__ __forceinline__ void mma_tf32(float4& d, const unsigned* a, const unsigned* b) {
    asm("mma.sync.aligned.m16n8k8.row.col.f32.tf32.tf32.f32 "
        "{%0,%1,%2,%3}, {%4,%5,%6,%7}, {%8,%9}, {%0,%1,%2,%3};"
        : "+f"(d.x), "+f"(d.y), "+f"(d.z), "+f"(d.w)
        : "r"(a[0]), "r"(a[1]), "r"(a[2]), "r"(a[3]),
          "r"(b[0]), "r"(b[1]));
}

#define AS_STR 20
#define BS_STR 136

template<int EPI>
__global__ void __launch_bounds__(256, 2)
mma_gemm_kernel(const float* __restrict__ A, const float* __restrict__ B,
                const float* __restrict__ bias, float* __restrict__ C,
                int M, int N, int K) {
    __shared__ float As[2][128][AS_STR];
    __shared__ float Bs[2][16][BS_STR];
    const int tid = threadIdx.x;
    const int bm = blockIdx.y, bn = blockIdx.x;
    const int lane = tid & 31;
    const int g  = lane >> 2;      // 0..7
    const int tg = lane & 3;       // 0..3
    const int wid = tid >> 5;
    const int wm = wid >> 2;       // 0..1
    const int wn = wid & 3;        // 0..3

    const float* Ab = A + (size_t)bm * 128 * K;
    const float* Bb = B + (size_t)bn * 128;

    const int arow = tid >> 1;            // 0..127
    const int acol = (tid & 1) * 8;       // 0 or 8
    const int brow = tid >> 4;            // 0..15
    const int bcol = (tid & 15) * 8;      // 0..120

    // prefetch registers
    float4 ra0 = *(const float4*)(Ab + (size_t)arow * K + acol);
    float4 ra1 = *(const float4*)(Ab + (size_t)arow * K + acol + 4);
    float4 rb0 = *(const float4*)(Bb + (size_t)brow * N + bcol);
    float4 rb1 = *(const float4*)(Bb + (size_t)brow * N + bcol + 4);

    float4 acc[4][4];
    #pragma unroll
    for (int i = 0; i < 4; i++)
        #pragma unroll
        for (int j = 0; j < 4; j++)
            acc[i][j] = make_float4(0.f, 0.f, 0.f, 0.f);

    const int NIT = K >> 4;
    int p = 0;
    for (int it = 0; it < NIT; ++it) {
        // round + store staged tile
        float4 t0, t1;
        t0.x = tf32r(ra0.x); t0.y = tf32r(ra0.y); t0.z = tf32r(ra0.z); t0.w = tf32r(ra0.w);
        t1.x = tf32r(ra1.x); t1.y = tf32r(ra1.y); t1.z = tf32r(ra1.z); t1.w = tf32r(ra1.w);
        *(float4*)&As[p][arow][acol]     = t0;
        *(float4*)&As[p][arow][acol + 4] = t1;
        t0.x = tf32r(rb0.x); t0.y = tf32r(rb0.y); t0.z = tf32r(rb0.z); t0.w = tf32r(rb0.w);
        t1.x = tf32r(rb1.x); t1.y = tf32r(rb1.y); t1.z = tf32r(rb1.z); t1.w = tf32r(rb1.w);
        *(float4*)&Bs[p][brow][bcol]     = t0;
        *(float4*)&Bs[p][brow][bcol + 4] = t1;
        __syncthreads();

        if (it + 1 < NIT) {
            const int k0 = (it + 1) << 4;
            ra0 = *(const float4*)(Ab + (size_t)arow * K + k0 + acol);
            ra1 = *(const float4*)(Ab + (size_t)arow * K + k0 + acol + 4);
            rb0 = *(const float4*)(Bb + (size_t)(k0 + brow) * N + bcol);
            rb1 = *(const float4*)(Bb + (size_t)(k0 + brow) * N + bcol + 4);
        }

        #pragma unroll
        for (int kk = 0; kk < 16; kk += 8) {
            unsigned af[4][4], bf[4][2];
            #pragma unroll
            for (int mt = 0; mt < 4; mt++) {
                const float* ab = &As[p][wm * 64 + mt * 16 + g][kk + tg];
                af[mt][0] = __float_as_uint(ab[0]);
                af[mt][1] = __float_as_uint(ab[8 * AS_STR]);
                af[mt][2] = __float_as_uint(ab[4]);
                af[mt][3] = __float_as_uint(ab[8 * AS_STR + 4]);
            }
            #pragma unroll
            for (int nt = 0; nt < 4; nt++) {
                const float* bb = &Bs[p][kk + tg][wn * 32 + nt * 8 + g];
                bf[nt][0] = __float_as_uint(bb[0]);
                bf[nt][1] = __float_as_uint(bb[4 * BS_STR]);
            }
            #pragma unroll
            for (int mt = 0; mt < 4; mt++)
                #pragma unroll
                for (int nt = 0; nt < 4; nt++)
                    mma_tf32(acc[mt][nt], af[mt], bf[nt]);
        }
        p ^= 1;
    }

    // epilogue: c0 (g, tg*2), c1 (g, tg*2+1), c2 (g+8, tg*2), c3 (g+8, tg*2+1)
    #pragma unroll
    for (int mt = 0; mt < 4; mt++) {
        const int row0 = bm * 128 + wm * 64 + mt * 16 + g;
        #pragma unroll
        for (int nt = 0; nt < 4; nt++) {
            const int col = bn * 128 + wn * 32 + nt * 8 + tg * 2;
            float4 d = acc[mt][nt];
            if (EPI >= 1) {
                const float b0 = bias[col], b1 = bias[col + 1];
                d.x += b0; d.y += b1; d.z += b0; d.w += b1;
            }
            if (EPI == 2) {
                d.x = d.x > 0.f ? d.x : expm1f(d.x);
                d.y = d.y > 0.f ? d.y : expm1f(d.y);
                d.z = d.z > 0.f ? d.z : expm1f(d.z);
                d.w = d.w > 0.f ? d.w : expm1f(d.w);
            }
            *(float2*)&C[(size_t)row0 * N + col]       = make_float2(d.x, d.y);
            *(float2*)&C[(size_t)(row0 + 8) * N + col] = make_float2(d.z, d.w);
        }
    }
}

// ---------------- k-feature pre-pass: dash + diag + global max(dash) --------
__global__ void feat_dash_k_kernel(const float* __restrict__ k,
                                   const float* __restrict__ proj,
                                   float* __restrict__ kdash,
                                   float* __restrict__ diagbuf) {
    __shared__ float pr[64][65];
    __shared__ float row[4][64];
    __shared__ float red[256];
    const int tx = threadIdx.x, ty = threadIdx.y;
    const int tid = ty * 64 + tx;
    for (int i = tid; i < 64 * 64; i += 256) pr[i >> 6][i & 63] = tf32r(proj[i]);
    const size_t r0 = (size_t)blockIdx.x * 4;
    row[ty][tx] = k[r0 * 64 + ty * 64 + tx];
    __syncthreads();
    float dot = 0.f, ss = 0.f;
    #pragma unroll
    for (int j = 0; j < 64; j++) {
        float v = row[ty][j];
        dot = fmaf(tf32r(v * DN_C), pr[tx][j], dot);
        ss  = fmaf(v, v, ss);
    }
    kdash[(r0 + ty) * 64 + tx] = dot;
    if (tx == 0) diagbuf[r0 + ty] = ss * (DN_C * DN_C * 0.5f);
    red[tid] = dot;
    __syncthreads();
    for (int s = 128; s > 0; s >>= 1) {
        if (tid < s) red[tid] = fmaxf(red[tid], red[tid + s]);
        __syncthreads();
    }
    if (tid == 0) atomicMax(&g_kmax_enc, enc_f(red[0]));
}

__global__ void exp_k_kernel(float* __restrict__ kf, const float* __restrict__ diagbuf) {
    const float mx = dec_f(g_kmax_enc);
    size_t i = (size_t)blockIdx.x * 256 + threadIdx.x;
    float d = diagbuf[i >> 6];
    kf[i] = RATIO * (expf(kf[i] - d - mx) + EPSK);
}

// ---------------- q-feature: dash + per-row max(dash) + exp, one pass -------
__global__ void feat_q_kernel(const float* __restrict__ q,
                              const float* __restrict__ proj,
                              float* __restrict__ qf) {
    __shared__ float pr[64][65];
    __shared__ float row[4][64];
    __shared__ float red[4][64];
    const int tx = threadIdx.x, ty = threadIdx.y;
    const int tid = ty * 64 + tx;
    for (int i = tid; i < 64 * 64; i += 256) pr[i >> 6][i & 63] = tf32r(proj[i]);
    const size_t r0 = (size_t)blockIdx.x * 4;
    row[ty][tx] = q[r0 * 64 + ty * 64 + tx];
    __syncthreads();
    float dot = 0.f, ss = 0.f;
    #pragma unroll
    for (int j = 0; j < 64; j++) {
        float v = row[ty][j];
        dot = fmaf(tf32r(v * DN_C), pr[tx][j], dot);
        ss  = fmaf(v, v, ss);
    }
    float diag = ss * (DN_C * DN_C * 0.5f);
    red[ty][tx] = dot;
    __syncthreads();
    for (int s = 32; s > 0; s >>= 1) {
        if (tx < s) red[ty][tx] = fmaxf(red[ty][tx], red[ty][tx + s]);
        __syncthreads();
    }
    float mx = red[ty][0];
    qf[(r0 + ty) * 64 + tx] = RATIO * (expf(dot - diag - mx) + EPSK);
}

// ---------------- kv partials: chunked over SEQ for full-chip occupancy -----
__global__ void kv_part_kernel(const float* __restrict__ kf,
                               const float* __restrict__ v,
                               float* __restrict__ kvp,
                               float* __restrict__ ksp) {
    __shared__ float kfs[16][64];
    __shared__ float vs[16][64];
    const int bh = blockIdx.x;
    const int ch = blockIdx.y;
    const int b = bh >> 4, h = bh & 15;
    const float* kfb = kf + ((size_t)b * SEQ * NH + h) * 64;
    const float* vb  = v  + ((size_t)b * SEQ * NH + h) * 64;
    const int tid = threadIdx.x;
    const int tm = (tid >> 4) * 4, td = (tid & 15) * 4;
    const int ln = tid >> 6, lm = tid & 63;
    float acc[4][4] = {};
    float asum[4] = {};
    const int nlo = ch * (SEQ / KVCH), nhi = nlo + SEQ / KVCH;
    for (int n0 = nlo; n0 < nhi; n0 += 16) {
        __syncthreads();
        #pragma unroll
        for (int it = 0; it < 4; it++) {
            int nn = ln + it * 4;
            size_t off = (size_t)(n0 + nn) * (NH * 64) + lm;
            kfs[nn][lm] = kfb[off];
            vs[nn][lm]  = vb[off];
        }
        __syncthreads();
        #pragma unroll
        for (int nn = 0; nn < 16; nn++) {
            float a[4], ar[4], bb[4];
            #pragma unroll
            for (int i = 0; i < 4; i++) { a[i] = kfs[nn][tm + i]; ar[i] = tf32r(a[i]); }
            #pragma unroll
            for (int j = 0; j < 4; j++) bb[j] = tf32r(vs[nn][td + j]);
            #pragma unroll
            for (int i = 0; i < 4; i++) {
                if (td == 0) asum[i] += a[i];
                #pragma unroll
                for (int j = 0; j < 4; j++)
                    acc[i][j] = fmaf(ar[i], bb[j], acc[i][j]);
            }
        }
    }
    float* kvb = kvp + ((size_t)ch * 64 + bh) * 64 * 64;
    #pragma unroll
    for (int i = 0; i < 4; i++)
        #pragma unroll
        for (int j = 0; j < 4; j++)
            kvb[(tm + i) * 64 + td + j] = acc[i][j];
    if ((tid & 15) == 0)
        #pragma unroll
        for (int i = 0; i < 4; i++) ksp[((size_t)ch * 64 + bh) * 64 + tm + i] = asum[i];
}

__global__ void kv_reduce_kernel(const float* __restrict__ kvp,
                                 const float* __restrict__ ksp,
                                 float* __restrict__ kv,
                                 float* __restrict__ ksum) {
    const int bh = blockIdx.x;
    const int tid = threadIdx.x;
    for (int i = tid; i < 64 * 64; i += 256) {
        float s = 0.f;
        #pragma unroll
        for (int c = 0; c < KVCH; c++)
            s += kvp[((size_t)c * 64 + bh) * 4096 + i];
        kv[(size_t)bh * 4096 + i] = s;
    }
    if (tid < 64) {
        float s = 0.f;
        #pragma unroll
        for (int c = 0; c < KVCH; c++)
            s += ksp[((size_t)c * 64 + bh) * 64 + tid];
        ksum[bh * 64 + tid] = s;
    }
}

// ---------------- attn[b,n,h,d] = (qf . kv[:,d]) / (qf . ksum) --------------
__global__ void attn_kernel(const float* __restrict__ qf,
                            const float* __restrict__ kv,
                            const float* __restrict__ ksum,
                            float* __restrict__ attn) {
    __shared__ float kvs[64][65];
    __shared__ float kss[64];
    __shared__ float qs[16][64];
    const int bh = blockIdx.x;
    const int b = bh >> 4, h = bh & 15;
    const int n0 = blockIdx.y * 16;
    const int tid = threadIdx.x;
    for (int i = tid; i < 64 * 64; i += 256)
        kvs[i >> 6][i & 63] = tf32r(kv[(size_t)bh * 4096 + i]);
    if (tid < 64) kss[tid] = tf32r(ksum[bh * 64 + tid]);
    const float* qfb = qf + ((size_t)b * SEQ * NH + h) * 64;
    const int ln = tid >> 6, lm = tid & 63;
    #pragma unroll
    for (int it = 0; it < 4; it++)
        qs[ln + it * 4][lm] = tf32r(qfb[(size_t)(n0 + ln + it * 4) * (NH * 64) + lm]);
    __syncthreads();
    const int d = tid & 63;
    const int r = tid >> 6;
    float* ab = attn + ((size_t)b * SEQ * NH + h) * 64;
    #pragma unroll
    for (int it = 0; it < 4; it++) {
        int nn = r + it * 4;
        float num = 0.f, den = 0.f;
        #pragma unroll
        for (int m = 0; m < 64; m++) {
            float qv = qs[nn][m];
            num = fmaf(qv, kvs[m][d], num);
            den = fmaf(qv, kss[m], den);
        }
        ab[(size_t)(n0 + nn) * (NH * 64) + d] = num / den;
    }
}

// ---------------- LayerNorm(a + b) * g + beta, row width 1024 ---------------
__global__ void ln_kernel(const float* __restrict__ a, const float* __restrict__ bres,
                          const float* __restrict__ g, const float* __restrict__ beta,
                          float* __restrict__ out) {
    __shared__ float red[2][8];
    const size_t row = blockIdx.x;
    const int tid = threadIdx.x;  // 256
    float4 x = ((const float4*)(a    + row * DIM))[tid];
    float4 y = ((const float4*)(bres + row * DIM))[tid];
    float4 s;
    s.x = x.x + y.x; s.y = x.y + y.y; s.z = x.z + y.z; s.w = x.w + y.w;
    float sum = s.x + s.y + s.z + s.w;
    float ssq = s.x * s.x + s.y * s.y + s.z * s.z + s.w * s.w;
    #pragma unroll
    for (int o = 16; o > 0; o >>= 1) {
        sum += __shfl_xor_sync(~0u, sum, o);
        ssq += __shfl_xor_sync(~0u, ssq, o);
    }
    const int w = tid >> 5, l = tid & 31;
    if (l == 0) { red[0][w] = sum; red[1][w] = ssq; }
    __syncthreads();
    sum = 0.f; ssq = 0.f;
    #pragma unroll
    for (int i = 0; i < 8; i++) { sum += red[0][i]; ssq += red[1][i]; }
    const float mu = sum * (1.f / DIM);
    const float var = ssq * (1.f / DIM) - mu * mu;
    const float rs = rsqrtf(var + EPSLN);
    float4 gg = ((const float4*)g)[tid];
    float4 bb = ((const float4*)beta)[tid];
    float4 o;
    o.x = (s.x - mu) * rs * gg.x + bb.x;
    o.y = (s.y - mu) * rs * gg.y + bb.y;
    o.z = (s.z - mu) * rs * gg.z + bb.z;
    o.w = (s.w - mu) * rs * gg.w + bb.w;
    ((float4*)(out + row * DIM))[tid] = o;
}

// ---------------- launcher ---------------------------------------------------
extern "C" void kernel_launch(void* const* d_in, const int* in_sizes, int n_in,
                              void* d_out, int out_size) {
    const float* x     = (const float*)d_in[0];
    const float* Wq    = (const float*)d_in[1];
    const float* Wk    = (const float*)d_in[2];
    const float* Wv    = (const float*)d_in[3];
    const float* Wo    = (const float*)d_in[4];
    const float* proj  = (const float*)d_in[5];
    const float* W1    = (const float*)d_in[6];
    const float* b1    = (const float*)d_in[7];
    const float* W2    = (const float*)d_in[8];
    const float* b2    = (const float*)d_in[9];
    const float* ln1g  = (const float*)d_in[10];
    const float* ln1b  = (const float*)d_in[11];
    const float* ln2g  = (const float*)d_in[12];
    const float* ln2b  = (const float*)d_in[13];
    float* out = (float*)d_out;

    float *pq, *pk, *pv, *pqf, *pkf, *pdiag, *pattn, *pao, *pout1, *pffn, *ph;
    float *pkv, *pksum, *pkvp, *pksp;
    cudaGetSymbolAddress((void**)&pq,    g_q);
    cudaGetSymbolAddress((void**)&pk,    g_k);
    cudaGetSymbolAddress((void**)&pv,    g_v);
    cudaGetSymbolAddress((void**)&pqf,   g_qf);
    cudaGetSymbolAddress((void**)&pkf,   g_kf);
    cudaGetSymbolAddress((void**)&pdiag, g_diag);
    cudaGetSymbolAddress((void**)&pattn, g_attn);
    cudaGetSymbolAddress((void**)&pao,   g_ao);
    cudaGetSymbolAddress((void**)&pout1, g_out1);
    cudaGetSymbolAddress((void**)&pffn,  g_ffn);
    cudaGetSymbolAddress((void**)&ph,    g_h);
    cudaGetSymbolAddress((void**)&pkv,   g_kv);
    cudaGetSymbolAddress((void**)&pksum, g_ksum);
    cudaGetSymbolAddress((void**)&pkvp,  g_kvp);
    cudaGetSymbolAddress((void**)&pksp,  g_ksp);

    // 1) QKV projections: [16384,1024] x [1024,1024]
    dim3 g_dk(DIM / 128, ROWS / 128);
    mma_gemm_kernel<0><<<g_dk, 256>>>(x, Wq, nullptr, pq, ROWS, DIM, DIM);
    mma_gemm_kernel<0><<<g_dk, 256>>>(x, Wk, nullptr, pk, ROWS, DIM, DIM);
    mma_gemm_kernel<0><<<g_dk, 256>>>(x, Wv, nullptr, pv, ROWS, DIM, DIM);

    // 2) k-feature dash + diag + global max(dash)
    init_max_kernel<<<1, 1>>>();
    feat_dash_k_kernel<<<FROWS / 4, dim3(64, 4)>>>(pk, proj, pkf, pdiag);
    exp_k_kernel<<<(ROWS * DIM) / 256, 256>>>(pkf, pdiag);

    // 3) q-features (row max local)
    feat_q_kernel<<<FROWS / 4, dim3(64, 4)>>>(pq, proj, pqf);

    // 4) kv + ksum (chunked partials, deterministic reduce)
    kv_part_kernel<<<dim3(BATCH * NH, KVCH), 256>>>(pkf, pv, pkvp, pksp);
    kv_reduce_kernel<<<BATCH * NH, 256>>>(pkvp, pksp, pkv, pksum);

    // 5) attention combine -> attn buffer [16384, 1024]
    attn_kernel<<<dim3(BATCH * NH, SEQ / 16), 256>>>(pqf, pkv, pksum, pattn);

    // 6) output projection Wo
    mma_gemm_kernel<0><<<g_dk, 256>>>(pattn, Wo, nullptr, pao, ROWS, DIM, DIM);

    // 7) LN1(x + attn_out)
    ln_kernel<<<ROWS, 256>>>(x, pao, ln1g, ln1b, pout1);

    // 8) FFN: h = elu(out1 @ W1 + b1)
    dim3 g_f1(DFF / 128, ROWS / 128);
    mma_gemm_kernel<2><<<g_f1, 256>>>(pout1, W1, b1, ph, ROWS, DFF, DIM);

    // 9) ffn = h @ W2 + b2
    mma_gemm_kernel<1><<<g_dk, 256>>>(ph, W2, b2, pffn, ROWS, DIM, DFF);

    // 10) LN2(out1 + ffn) -> output
    ln_kernel<<<ROWS, 256>>>(pout1, pffn, ln2g, ln2b, out);

    (void)in_sizes; (void)n_in; (void)out_size;
}

// round 17
// speedup vs baseline: 2.1670x; 1.0031x over previous
#include <cuda_runtime.h>
#include <cuda_bf16.h>
#include <math.h>
#include <limits.h>

// Problem constants
#define BATCH 4
#define SEQ   4096
#define DIM   1024
#define NH    16
#define DH    64
#define DFF   4096
#define MFEAT 64
#define ROWS  (BATCH*SEQ)          // 16384
#define FROWS (BATCH*SEQ*NH)       // 262144 feature rows
#define DN_C  0.35355339059327373f // 64^{-1/4}
#define RATIO 0.125f               // 1/sqrt(64)
#define EPSK  1e-6f
#define EPSLN 1e-6f
#define KVCH  8                    // kv partial chunks

// ---------------- scratch (device globals; no runtime allocation) -----------
__device__ float g_q   [ROWS*DIM];
__device__ float g_k   [ROWS*DIM];
__device__ float g_v   [ROWS*DIM];
__device__ float g_qf  [ROWS*DIM];
__device__ float g_kf  [ROWS*DIM];   // k dash, then kf in place
__device__ float g_diag[FROWS];
__device__ float g_attn[ROWS*DIM];
__device__ float g_ao  [ROWS*DIM];
__device__ float g_out1[ROWS*DIM];
__device__ float g_ffn [ROWS*DIM];
__device__ float g_h   [ROWS*DFF];
__device__ float g_kv  [BATCH*NH*MFEAT*DH];
__device__ float g_ksum[BATCH*NH*MFEAT];
__device__ float g_kvp [KVCH*BATCH*NH*MFEAT*DH];
__device__ float g_ksp [KVCH*BATCH*NH*MFEAT];
__device__ int   g_kmax_enc;

// TF32 rounding (matches XLA/cuBLAS fp32->tf32 operand rounding)
__device__ __forceinline__ float tf32r(float x) {
    float r;
    asm("cvt.rna.tf32.f32 %0, %1;" : "=f"(r) : "f"(x));
    return r;
}

__device__ __forceinline__ int enc_f(float f) {
    int i = __float_as_int(f);
    return i >= 0 ? i : (i ^ 0x7fffffff);
}
__device__ __forceinline__ float dec_f(int e) {
    int i = e >= 0 ? e : (e ^ 0x7fffffff);
    return __int_as_float(i);
}

__global__ void init_max_kernel() { g_kmax_enc = INT_MIN; }

// ---------------- tf32 tensor-core GEMM -------------------------------------
// C[MxN] = A[MxK] * B[KxN], row-major. Operands tf32(rna)-rounded, fp32 accum
// (bit-compatible with XLA tf32 matmul). 128x128 block tile, BK=16,
// 8 warps (2x4), warp tile 64x32 via m16n8k8 fragments. Double-buffered smem.
// EPI: 0 = none, 1 = +bias, 2 = +bias then ELU
__device__ __forceinline__ void mma_tf32(float4& d, const unsigned* a, const unsigned* b) {
    asm("mma.sync.aligned.m16n8k8.row.col.f32.tf32.tf32.f32 "
        "{%0,%1,%2,%3}, {%4,%5,%6,%7}, {%8,%9}, {%0,%1,%2,%3};"
        : "+f"(d.x), "+f"(d.y), "+f"(d.z), "+f"(d.w)
        : "r"(a[0]), "r"(a[1]), "r"(a[2]), "r"(a[3]),
          "r"(b[0]), "r"(b[1]));
}

#define AS_STR 20
#define BS_STR 136

template<int EPI>
__global__ void __launch_bounds__(256, 2)
mma_gemm_kernel(const float* __restrict__ A, const float* __restrict__ B,
                const float* __restrict__ bias, float* __restrict__ C,
                int M, int N, int K) {
    __shared__ float As[2][128][AS_STR];
    __shared__ float Bs[2][16][BS_STR];
    const int tid = threadIdx.x;
    const int bm = blockIdx.y, bn = blockIdx.x;
    const int lane = tid & 31;
    const int g  = lane >> 2;      // 0..7
    const int tg = lane & 3;       // 0..3
    const int wid = tid >> 5;
    const int wm = wid >> 2;       // 0..1
    const int wn = wid & 3;        // 0..3

    const float* Ab = A + (size_t)bm * 128 * K;
    const float* Bb = B + (size_t)bn * 128;

    const int arow = tid >> 1;            // 0..127
    const int acol = (tid & 1) * 8;       // 0 or 8
    const int brow = tid >> 4;            // 0..15
    const int bcol = (tid & 15) * 8;      // 0..120

    // prefetch registers
    float4 ra0 = *(const float4*)(Ab + (size_t)arow * K + acol);
    float4 ra1 = *(const float4*)(Ab + (size_t)arow * K + acol + 4);
    float4 rb0 = *(const float4*)(Bb + (size_t)brow * N + bcol);
    float4 rb1 = *(const float4*)(Bb + (size_t)brow * N + bcol + 4);

    float4 acc[4][4];
    #pragma unroll
    for (int i = 0; i < 4; i++)
        #pragma unroll
        for (int j = 0; j < 4; j++)
            acc[i][j] = make_float4(0.f, 0.f, 0.f, 0.f);

    const int NIT = K >> 4;
    int p = 0;
    for (int it = 0; it < NIT; ++it) {
        // round + store staged tile
        float4 t0, t1;
        t0.x = tf32r(ra0.x); t0.y = tf32r(ra0.y); t0.z = tf32r(ra0.z); t0.w = tf32r(ra0.w);
        t1.x = tf32r(ra1.x); t1.y = tf32r(ra1.y); t1.z = tf32r(ra1.z); t1.w = tf32r(ra1.w);
        *(float4*)&As[p][arow][acol]     = t0;
        *(float4*)&As[p][arow][acol + 4] = t1;
        t0.x = tf32r(rb0.x); t0.y = tf32r(rb0.y); t0.z = tf32r(rb0.z); t0.w = tf32r(rb0.w);
        t1.x = tf32r(rb1.x); t1.y = tf32r(rb1.y); t1.z = tf32r(rb1.z); t1.w = tf32r(rb1.w);
        *(float4*)&Bs[p][brow][bcol]     = t0;
        *(float4*)&Bs[p][brow][bcol + 4] = t1;
        __syncthreads();

        if (it + 1 < NIT) {
            const int k0 = (it + 1) << 4;
            ra0 = *(const float4*)(Ab + (size_t)arow * K + k0 + acol);
            ra1 = *(const float4*)(Ab + (size_t)arow * K + k0 + acol + 4);
            rb0 = *(const float4*)(Bb + (size_t)(k0 + brow) * N + bcol);
            rb1 = *(const float4*)(Bb + (size_t)(k0 + brow) * N + bcol + 4);
        }

        #pragma unroll
        for (int kk = 0; kk < 16; kk += 8) {
            unsigned af[4][4], bf[4][2];
            #pragma unroll
            for (int mt = 0; mt < 4; mt++) {
                const float* ab = &As[p][wm * 64 + mt * 16 + g][kk + tg];
                af[mt][0] = __float_as_uint(ab[0]);
                af[mt][1] = __float_as_uint(ab[8 * AS_STR]);
                af[mt][2] = __float_as_uint(ab[4]);
                af[mt][3] = __float_as_uint(ab[8 * AS_STR + 4]);
            }
            #pragma unroll
            for (int nt = 0; nt < 4; nt++) {
                const float* bb = &Bs[p][kk + tg][wn * 32 + nt * 8 + g];
                bf[nt][0] = __float_as_uint(bb[0]);
                bf[nt][1] = __float_as_uint(bb[4 * BS_STR]);
            }
            #pragma unroll
            for (int mt = 0; mt < 4; mt++)
                #pragma unroll
                for (int nt = 0; nt < 4; nt++)
                    mma_tf32(acc[mt][nt], af[mt], bf[nt]);
        }
        p ^= 1;
    }

    // epilogue: c0 (g, tg*2), c1 (g, tg*2+1), c2 (g+8, tg*2), c3 (g+8, tg*2+1)
    #pragma unroll
    for (int mt = 0; mt < 4; mt++) {
        const int row0 = bm * 128 + wm * 64 + mt * 16 + g;
        #pragma unroll
        for (int nt = 0; nt < 4; nt++) {
            const int col = bn * 128 + wn * 32 + nt * 8 + tg * 2;
            float4 d = acc[mt][nt];
            if (EPI >= 1) {
                const float b0 = bias[col], b1 = bias[col + 1];
                d.x += b0; d.y += b1; d.z += b0; d.w += b1;
            }
            if (EPI == 2) {
                d.x = d.x > 0.f ? d.x : expm1f(d.x);
                d.y = d.y > 0.f ? d.y : expm1f(d.y);
                d.z = d.z > 0.f ? d.z : expm1f(d.z);
                d.w = d.w > 0.f ? d.w : expm1f(d.w);
            }
            *(float2*)&C[(size_t)row0 * N + col]       = make_float2(d.x, d.y);
            *(float2*)&C[(size_t)(row0 + 8) * N + col] = make_float2(d.z, d.w);
        }
    }
}

// ---------------- k-feature pre-pass: dash + diag + global max(dash) --------
__global__ void feat_dash_k_kernel(const float* __restrict__ k,
                                   const float* __restrict__ proj,
                                   float* __restrict__ kdash,
                                   float* __restrict__ diagbuf) {
    __shared__ float pr[64][65];
    __shared__ float row[4][64];
    __shared__ float red[256];
    const int tx = threadIdx.x, ty = threadIdx.y;
    const int tid = ty * 64 + tx;
    for (int i = tid; i < 64 * 64; i += 256) pr[i >> 6][i & 63] = tf32r(proj[i]);
    const size_t r0 = (size_t)blockIdx.x * 4;
    row[ty][tx] = k[r0 * 64 + ty * 64 + tx];
    __syncthreads();
    float dot = 0.f, ss = 0.f;
    #pragma unroll
    for (int j = 0; j < 64; j++) {
        float v = row[ty][j];
        dot = fmaf(tf32r(v * DN_C), pr[tx][j], dot);
        ss  = fmaf(v, v, ss);
    }
    kdash[(r0 + ty) * 64 + tx] = dot;
    if (tx == 0) diagbuf[r0 + ty] = ss * (DN_C * DN_C * 0.5f);
    red[tid] = dot;
    __syncthreads();
    for (int s = 128; s > 0; s >>= 1) {
        if (tid < s) red[tid] = fmaxf(red[tid], red[tid + s]);
        __syncthreads();
    }
    if (tid == 0) atomicMax(&g_kmax_enc, enc_f(red[0]));
}

__global__ void exp_k_kernel(float* __restrict__ kf, const float* __restrict__ diagbuf) {
    const float mx = dec_f(g_kmax_enc);
    size_t i = (size_t)blockIdx.x * 256 + threadIdx.x;
    float d = diagbuf[i >> 6];
    kf[i] = RATIO * (expf(kf[i] - d - mx) + EPSK);
}

// ---------------- q-feature: dash + per-row max(dash) + exp, one pass -------
__global__ void feat_q_kernel(const float* __restrict__ q,
                              const float* __restrict__ proj,
                              float* __restrict__ qf) {
    __shared__ float pr[64][65];
    __shared__ float row[4][64];
    __shared__ float red[4][64];
    const int tx = threadIdx.x, ty = threadIdx.y;
    const int tid = ty * 64 + tx;
    for (int i = tid; i < 64 * 64; i += 256) pr[i >> 6][i & 63] = tf32r(proj[i]);
    const size_t r0 = (size_t)blockIdx.x * 4;
    row[ty][tx] = q[r0 * 64 + ty * 64 + tx];
    __syncthreads();
    float dot = 0.f, ss = 0.f;
    #pragma unroll
    for (int j = 0; j < 64; j++) {
        float v = row[ty][j];
        dot = fmaf(tf32r(v * DN_C), pr[tx][j], dot);
        ss  = fmaf(v, v, ss);
    }
    float diag = ss * (DN_C * DN_C * 0.5f);
    red[ty][tx] = dot;
    __syncthreads();
    for (int s = 32; s > 0; s >>= 1) {
        if (tx < s) red[ty][tx] = fmaxf(red[ty][tx], red[ty][tx + s]);
        __syncthreads();
    }
    float mx = red[ty][0];
    qf[(r0 + ty) * 64 + tx] = RATIO * (expf(dot - diag - mx) + EPSK);
}

// ---------------- kv partials: chunked over SEQ for full-chip occupancy -----
__global__ void kv_part_kernel(const float* __restrict__ kf,
                               const float* __restrict__ v,
                               float* __restrict__ kvp,
                               float* __restrict__ ksp) {
    __shared__ float kfs[16][64];
    __shared__ float vs[16][64];
    const int bh = blockIdx.x;
    const int ch = blockIdx.y;
    const int b = bh >> 4, h = bh & 15;
    const float* kfb = kf + ((size_t)b * SEQ * NH + h) * 64;
    const float* vb  = v  + ((size_t)b * SEQ * NH + h) * 64;
    const int tid = threadIdx.x;
    const int tm = (tid >> 4) * 4, td = (tid & 15) * 4;
    const int ln = tid >> 6, lm = tid & 63;
    float acc[4][4] = {};
    float asum[4] = {};
    const int nlo = ch * (SEQ / KVCH), nhi = nlo + SEQ / KVCH;
    for (int n0 = nlo; n0 < nhi; n0 += 16) {
        __syncthreads();
        #pragma unroll
        for (int it = 0; it < 4; it++) {
            int nn = ln + it * 4;
            size_t off = (size_t)(n0 + nn) * (NH * 64) + lm;
            kfs[nn][lm] = kfb[off];
            vs[nn][lm]  = vb[off];
        }
        __syncthreads();
        #pragma unroll
        for (int nn = 0; nn < 16; nn++) {
            float a[4], ar[4], bb[4];
            #pragma unroll
            for (int i = 0; i < 4; i++) { a[i] = kfs[nn][tm + i]; ar[i] = tf32r(a[i]); }
            #pragma unroll
            for (int j = 0; j < 4; j++) bb[j] = tf32r(vs[nn][td + j]);
            #pragma unroll
            for (int i = 0; i < 4; i++) {
                if (td == 0) asum[i] += a[i];
                #pragma unroll
                for (int j = 0; j < 4; j++)
                    acc[i][j] = fmaf(ar[i], bb[j], acc[i][j]);
            }
        }
    }
    float* kvb = kvp + ((size_t)ch * 64 + bh) * 64 * 64;
    #pragma unroll
    for (int i = 0; i < 4; i++)
        #pragma unroll
        for (int j = 0; j < 4; j++)
            kvb[(tm + i) * 64 + td + j] = acc[i][j];
    if ((tid & 15) == 0)
        #pragma unroll
        for (int i = 0; i < 4; i++) ksp[((size_t)ch * 64 + bh) * 64 + tm + i] = asum[i];
}

__global__ void kv_reduce_kernel(const float* __restrict__ kvp,
                                 const float* __restrict__ ksp,
                                 float* __restrict__ kv,
                                 float* __restrict__ ksum) {
    const int bh = blockIdx.x;
    const int tid = threadIdx.x;
    for (int i = tid; i < 64 * 64; i += 256) {
        float s = 0.f;
        #pragma unroll
        for (int c = 0; c < KVCH; c++)
            s += kvp[((size_t)c * 64 + bh) * 4096 + i];
        kv[(size_t)bh * 4096 + i] = s;
    }
    if (tid < 64) {
        float s = 0.f;
        #pragma unroll
        for (int c = 0; c < KVCH; c++)
            s += ksp[((size_t)c * 64 + bh) * 64 + tid];
        ksum[bh * 64 + tid] = s;
    }
}

// ---------------- attn[b,n,h,d] = (qf . kv[:,d]) / (qf . ksum) --------------
__global__ void attn_kernel(const float* __restrict__ qf,
                            const float* __restrict__ kv,
                            const float* __restrict__ ksum,
                            float* __restrict__ attn) {
    __shared__ float kvs[64][65];
    __shared__ float kss[64];
    __shared__ float qs[16][64];
    const int bh = blockIdx.x;
    const int b = bh >> 4, h = bh & 15;
    const int n0 = blockIdx.y * 16;
    const int tid = threadIdx.x;
    for (int i = tid; i < 64 * 64; i += 256)
        kvs[i >> 6][i & 63] = tf32r(kv[(size_t)bh * 4096 + i]);
    if (tid < 64) kss[tid] = tf32r(ksum[bh * 64 + tid]);
    const float* qfb = qf + ((size_t)b * SEQ * NH + h) * 64;
    const int ln = tid >> 6, lm = tid & 63;
    #pragma unroll
    for (int it = 0; it < 4; it++)
        qs[ln + it * 4][lm] = tf32r(qfb[(size_t)(n0 + ln + it * 4) * (NH * 64) + lm]);
    __syncthreads();
    const int d = tid & 63;
    const int r = tid >> 6;
    float* ab = attn + ((size_t)b * SEQ * NH + h) * 64;
    #pragma unroll
    for (int it = 0; it < 4; it++) {
        int nn = r + it * 4;
        float num = 0.f, den = 0.f;
        #pragma unroll
        for (int m = 0; m < 64; m++) {
            float qv = qs[nn][m];
            num = fmaf(qv, kvs[m][d], num);
            den = fmaf(qv, kss[m], den);
        }
        ab[(size_t)(n0 + nn) * (NH * 64) + d] = num / den;
    }
}

// ---------------- LayerNorm(a + b) * g + beta, row width 1024 ---------------
__global__ void ln_kernel(const float* __restrict__ a, const float* __restrict__ bres,
                          const float* __restrict__ g, const float* __restrict__ beta,
                          float* __restrict__ out) {
    __shared__ float red[2][8];
    const size_t row = blockIdx.x;
    const int tid = threadIdx.x;  // 256
    float4 x = ((const float4*)(a    + row * DIM))[tid];
    float4 y = ((const float4*)(bres + row * DIM))[tid];
    float4 s;
    s.x = x.x + y.x; s.y = x.y + y.y; s.z = x.z + y.z; s.w = x.w + y.w;
    float sum = s.x + s.y + s.z + s.w;
    float ssq = s.x * s.x + s.y * s.y + s.z * s.z + s.w * s.w;
    #pragma unroll
    for (int o = 16; o > 0; o >>= 1) {
        sum += __shfl_xor_sync(~0u, sum, o);
        ssq += __shfl_xor_sync(~0u, ssq, o);
    }
    const int w = tid >> 5, l = tid & 31;
    if (l == 0) { red[0][w] = sum; red[1][w] = ssq; }
    __syncthreads();
    sum = 0.f; ssq = 0.f;
    #pragma unroll
    for (int i = 0; i < 8; i++) { sum += red[0][i]; ssq += red[1][i]; }
    const float mu = sum * (1.f / DIM);
    const float var = ssq * (1.f / DIM) - mu * mu;
    const float rs = rsqrtf(var + EPSLN);
    float4 gg = ((const float4*)g)[tid];
    float4 bb = ((const float4*)beta)[tid];
    float4 o;
    o.x = (s.x - mu) * rs * gg.x + bb.x;
    o.y = (s.y - mu) * rs * gg.y + bb.y;
    o.z = (s.z - mu) * rs * gg.z + bb.z;
    o.w = (s.w - mu) * rs * gg.w + bb.w;
    ((float4*)(out + row * DIM))[tid] = o;
}

// ---------------- launcher ---------------------------------------------------
extern "C" void kernel_launch(void* const* d_in, const int* in_sizes, int n_in,
                              void* d_out, int out_size) {
    const float* x     = (const float*)d_in[0];
    const float* Wq    = (const float*)d_in[1];
    const float* Wk    = (const float*)d_in[2];
    const float* Wv    = (const float*)d_in[3];
    const float* Wo    = (const float*)d_in[4];
    const float* proj  = (const float*)d_in[5];
    const float* W1    = (const float*)d_in[6];
    const float* b1    = (const float*)d_in[7];
    const float* W2    = (const float*)d_in[8];
    const float* b2    = (const float*)d_in[9];
    const float* ln1g  = (const float*)d_in[10];
    const float* ln1b  = (const float*)d_in[11];
    const float* ln2g  = (const float*)d_in[12];
    const float* ln2b  = (const float*)d_in[13];
    float* out = (float*)d_out;

    float *pq, *pk, *pv, *pqf, *pkf, *pdiag, *pattn, *pao, *pout1, *pffn, *ph;
    float *pkv, *pksum, *pkvp, *pksp;
    cudaGetSymbolAddress((void**)&pq,    g_q);
    cudaGetSymbolAddress((void**)&pk,    g_k);
    cudaGetSymbolAddress((void**)&pv,    g_v);
    cudaGetSymbolAddress((void**)&pqf,   g_qf);
    cudaGetSymbolAddress((void**)&pkf,   g_kf);
    cudaGetSymbolAddress((void**)&pdiag, g_diag);
    cudaGetSymbolAddress((void**)&pattn, g_attn);
    cudaGetSymbolAddress((void**)&pao,   g_ao);
    cudaGetSymbolAddress((void**)&pout1, g_out1);
    cudaGetSymbolAddress((void**)&pffn,  g_ffn);
    cudaGetSymbolAddress((void**)&ph,    g_h);
    cudaGetSymbolAddress((void**)&pkv,   g_kv);
    cudaGetSymbolAddress((void**)&pksum, g_ksum);
    cudaGetSymbolAddress((void**)&pkvp,  g_kvp);
    cudaGetSymbolAddress((void**)&pksp,  g_ksp);

    // 1) QKV projections: [16384,1024] x [1024,1024]
    dim3 g_dk(DIM / 128, ROWS / 128);
    mma_gemm_kernel<0><<<g_dk, 256>>>(x, Wq, nullptr, pq, ROWS, DIM, DIM);
    mma_gemm_kernel<0><<<g_dk, 256>>>(x, Wk, nullptr, pk, ROWS, DIM, DIM);
    mma_gemm_kernel<0><<<g_dk, 256>>>(x, Wv, nullptr, pv, ROWS, DIM, DIM);

    // 2) k-feature dash + diag + global max(dash)
    init_max_kernel<<<1, 1>>>();
    feat_dash_k_kernel<<<FROWS / 4, dim3(64, 4)>>>(pk, proj, pkf, pdiag);
    exp_k_kernel<<<(ROWS * DIM) / 256, 256>>>(pkf, pdiag);

    // 3) q-features (row max local)
    feat_q_kernel<<<FROWS / 4, dim3(64, 4)>>>(pq, proj, pqf);

    // 4) kv + ksum (chunked partials, deterministic reduce)
    kv_part_kernel<<<dim3(BATCH * NH, KVCH), 256>>>(pkf, pv, pkvp, pksp);
    kv_reduce_kernel<<<BATCH * NH, 256>>>(pkvp, pksp, pkv, pksum);

    // 5) attention combine -> attn buffer [16384, 1024]
    attn_kernel<<<dim3(BATCH * NH, SEQ / 16), 256>>>(pqf, pkv, pksum, pattn);

    // 6) output projection Wo
    mma_gemm_kernel<0><<<g_dk, 256>>>(pattn, Wo, nullptr, pao, ROWS, DIM, DIM);

    // 7) LN1(x + attn_out)
    ln_kernel<<<ROWS, 256>>>(x, pao, ln1g, ln1b, pout1);

    // 8) FFN: h = elu(out1 @ W1 + b1)
    dim3 g_f1(DFF / 128, ROWS / 128);
    mma_gemm_kernel<2><<<g_f1, 256>>>(pout1, W1, b1, ph, ROWS, DFF, DIM);

    // 9) ffn = h @ W2 + b2
    mma_gemm_kernel<1><<<g_dk, 256>>>(ph, W2, b2, pffn, ROWS, DIM, DFF);

    // 10) LN2(out1 + ffn) -> output
    ln_kernel<<<ROWS, 256>>>(pout1, pffn, ln2g, ln2b, out);

    (void)in_sizes; (void)n_in; (void)out_size;
}